// round 10
// baseline (speedup 1.0000x reference)
#include <cuda_runtime.h>
#include <cuda_bf16.h>
#include <stdint.h>

// Shapes fixed by setup_inputs
#define BATCH   2
#define S_LEN   4096
#define EMB     1024
#define NH      16
#define HD      64
#define QKV_N   3072      // per (b,s) row: [h][q64|k64|v64] -> col = h*192 + part*64 + d
#define WRAD    256

// GEMM tiling (mma.sync m16n8k8 tf32): 128x128 CTA, 64x32 warp tile, BK=32,
// 2 CTAs/SM, explicit fragment double-buffering.
#define BM 128
#define BN 128
#define BK 32
#define ASTR 36                          // 32 k + 4 pad
#define BSTR 132                         // 128 n + 4 pad
#define A_BYTES (128 * ASTR * 4)         // 18432
#define B_BYTES (BK * BSTR * 4)          // 16896
#define STG_BYTES (A_BYTES + B_BYTES)    // 35328
#define NSTAGE 3
#define GEMM_SMEM (NSTAGE * STG_BYTES)   // 105984 (2 CTAs/SM)

// Attention tiling: CTA = (b, h, 128 queries); 8 warps x 16 rows x 64 cols.
#define AQT 128
#define AKT 64
#define ATILES 10
#define QSTR 68
#define KSTR 68
#define VSTR 72
#define QS_OFF 0
#define KB_OFF (128 * QSTR)
#define VB_OFF (KB_OFF + 2 * 64 * KSTR)
#define ASMEM ((VB_OFF + 2 * 64 * VSTR) * 4)  // 106496 B -> 2 CTAs/SM

// ---------------- scratch (no allocs allowed) ----------------
__device__ float g_qkv[(size_t)BATCH * S_LEN * QKV_N];    // 96 MB
__device__ float g_ctx[(size_t)BATCH * S_LEN * EMB];      // 32 MB (tf32-rounded)
__device__ float g_x  [(size_t)BATCH * S_LEN * EMB];      // 32 MB
__device__ float g_wq [(size_t)EMB * QKV_N];              // 12 MB
__device__ float g_wo [(size_t)EMB * EMB];                //  4 MB

// ---------------- PTX helpers ----------------
static __device__ __forceinline__ uint32_t smem_u32(const void* p) {
    uint32_t a;
    asm("{ .reg .u64 t; cvta.to.shared.u64 t, %1; cvt.u32.u64 %0, t; }" : "=r"(a) : "l"(p));
    return a;
}
static __device__ __forceinline__ void cp_async16(uint32_t dst, const void* src) {
    asm volatile("cp.async.cg.shared.global [%0], [%1], 16;" :: "r"(dst), "l"(src) : "memory");
}
static __device__ __forceinline__ void cp_commit() {
    asm volatile("cp.async.commit_group;" ::: "memory");
}
template <int N> static __device__ __forceinline__ void cp_wait() {
    asm volatile("cp.async.wait_group %0;" :: "n"(N) : "memory");
}
static __device__ __forceinline__ void prefetch_l2(const void* p) {
    asm volatile("prefetch.global.L2 [%0];" :: "l"(p));
}
static __device__ __forceinline__ uint32_t cvt_tf32(float f) {
    uint32_t r; asm("cvt.rna.tf32.f32 %0, %1;" : "=r"(r) : "f"(f)); return r;
}
static __device__ __forceinline__ void mma_tf32(float* c, const uint32_t* a, const uint32_t* b) {
    asm("mma.sync.aligned.m16n8k8.row.col.f32.tf32.tf32.f32 "
        "{%0,%1,%2,%3}, {%4,%5,%6,%7}, {%8,%9}, {%0,%1,%2,%3};"
        : "+f"(c[0]), "+f"(c[1]), "+f"(c[2]), "+f"(c[3])
        : "r"(a[0]), "r"(a[1]), "r"(a[2]), "r"(a[3]), "r"(b[0]), "r"(b[1]));
}

// ---------------- tf32 pre-rounding pass ----------------
__global__ void round_tf32_k(const float* __restrict__ src, float* __restrict__ dst) {
    size_t i = ((size_t)blockIdx.x * 256 + threadIdx.x) * 4;
    float4 v = *(const float4*)(src + i);
    uint4 u = make_uint4(cvt_tf32(v.x), cvt_tf32(v.y), cvt_tf32(v.z), cvt_tf32(v.w));
    *(uint4*)(dst + i) = u;
}

// ---------------- tf32 mma.sync GEMM: C[M,N] = A[M,K] @ B[K,N] + bias --------
// 8 warps 2(m) x 4(n), warp tile 64x32, fragment double-buffering across kk.
static __device__ __forceinline__ void load_stage(
    const float* A, const float* B, int m0, int n0, int K, int N, int k0,
    uint32_t sb, int t)
{
#pragma unroll
    for (int i = 0; i < 4; i++) {          // A: 128 rows x 128B
        int idx = t + 256 * i;
        int r = idx >> 3, ch = idx & 7;
        cp_async16(sb + r * (ASTR * 4) + ch * 16,
                   A + (size_t)(m0 + r) * K + k0 + ch * 4);
    }
#pragma unroll
    for (int i = 0; i < 4; i++) {          // B: 32 rows x 512B
        int idx = t + 256 * i;
        int r = idx >> 5, ch = idx & 31;
        cp_async16(sb + A_BYTES + r * (BSTR * 4) + ch * 16,
                   B + (size_t)(k0 + r) * N + n0 + ch * 4);
    }
    cp_commit();
}

static __device__ __forceinline__ void load_frags(
    const uint32_t* As, const uint32_t* Bs, int kk,
    int wm, int wn, int gid, int tig,
    uint32_t a[4][4], uint32_t b[4][2])
{
#pragma unroll
    for (int i = 0; i < 4; i++) {
        int m = wm * 64 + i * 16 + gid;
        a[i][0] = As[m * ASTR + kk + tig];
        a[i][1] = As[(m + 8) * ASTR + kk + tig];
        a[i][2] = As[m * ASTR + kk + tig + 4];
        a[i][3] = As[(m + 8) * ASTR + kk + tig + 4];
    }
#pragma unroll
    for (int j = 0; j < 4; j++) {
        int n = wn * 32 + j * 8 + gid;
        b[j][0] = Bs[(kk + tig) * BSTR + n];
        b[j][1] = Bs[(kk + tig + 4) * BSTR + n];
    }
}

__global__ __launch_bounds__(256, 2) void gemm_tf32(
    const float* __restrict__ A, const float* __restrict__ B,
    const float* __restrict__ bias, float* __restrict__ C,
    int M, int N, int K)
{
    extern __shared__ char smem[];
    uint32_t sbase = smem_u32(smem);
    const int t = threadIdx.x;
    const int lane = t & 31, wid = t >> 5;
    const int wm = wid & 1, wn = wid >> 1;
    const int gid = lane >> 2, tig = lane & 3;
    const int m0 = blockIdx.y * BM;
    const int n0 = blockIdx.x * BN;

    float acc[4][4][4];
#pragma unroll
    for (int i = 0; i < 4; i++)
#pragma unroll
        for (int j = 0; j < 4; j++)
#pragma unroll
            for (int c = 0; c < 4; c++) acc[i][j][c] = 0.f;

    const int NS = K / BK;                 // 32
    load_stage(A, B, m0, n0, K, N, 0, sbase, t);
    load_stage(A, B, m0, n0, K, N, BK, sbase + STG_BYTES, t);

    for (int s = 0; s < NS; s++) {
        cp_wait<1>();
        __syncthreads();
        if (s + 2 < NS)
            load_stage(A, B, m0, n0, K, N, (s + 2) * BK,
                       sbase + ((s + 2) % NSTAGE) * STG_BYTES, t);

        const uint32_t* As = (const uint32_t*)(smem + (s % NSTAGE) * STG_BYTES);
        const uint32_t* Bs = (const uint32_t*)(smem + (s % NSTAGE) * STG_BYTES + A_BYTES);

        // fragment double-buffer: next kk's LDS issue before current kk's MMAs
        uint32_t af[2][4][4], bf[2][4][2];
        load_frags(As, Bs, 0, wm, wn, gid, tig, af[0], bf[0]);
#pragma unroll
        for (int kx = 0; kx < 4; kx++) {
            const int cur = kx & 1;
            if (kx < 3)
                load_frags(As, Bs, (kx + 1) * 8, wm, wn, gid, tig,
                           af[cur ^ 1], bf[cur ^ 1]);
#pragma unroll
            for (int i = 0; i < 4; i++)
#pragma unroll
                for (int j = 0; j < 4; j++)
                    mma_tf32(acc[i][j], af[cur][i], bf[cur][j]);
        }
    }

#pragma unroll
    for (int j = 0; j < 4; j++) {
        int n = n0 + wn * 32 + j * 8 + tig * 2;
        float2 bb = *(const float2*)(bias + n);
#pragma unroll
        for (int i = 0; i < 4; i++) {
            int m = m0 + wm * 64 + i * 16 + gid;
            *(float2*)(C + (size_t)m * N + n) =
                make_float2(acc[i][j][0] + bb.x, acc[i][j][1] + bb.y);
            *(float2*)(C + (size_t)(m + 8) * N + n) =
                make_float2(acc[i][j][2] + bb.x, acc[i][j][3] + bb.y);
        }
    }
}

// ---------------- banded sliding-window attention v2 (unchanged) ------------
static __device__ __forceinline__ void swa_load_kv(
    int b, int hh, int ks, uint32_t* sw, int pb, int t)
{
    const int kr = t >> 2, kc = (t & 3) * 16;
    const float* kp = g_qkv + ((size_t)(b * S_LEN + ks + kr) * NH + hh) * 192 + 64 + kc;
    uint32_t* kd = sw + KB_OFF + pb * (64 * KSTR) + kr * KSTR + kc;
    uint32_t* vd = sw + VB_OFF + pb * (64 * VSTR) + kr * VSTR + kc;
#pragma unroll
    for (int i = 0; i < 4; i++) {
        float4 kv = *(const float4*)(kp + 4 * i);
        float4 vv = *(const float4*)(kp + 64 + 4 * i);
        *(uint4*)(kd + 4 * i) =
            make_uint4(cvt_tf32(kv.x), cvt_tf32(kv.y), cvt_tf32(kv.z), cvt_tf32(kv.w));
        *(uint4*)(vd + 4 * i) =
            make_uint4(cvt_tf32(vv.x), cvt_tf32(vv.y), cvt_tf32(vv.z), cvt_tf32(vv.w));
    }
}

__global__ __launch_bounds__(256, 2) void swa_mma(void)
{
    extern __shared__ uint32_t sw[];
    const int t = threadIdx.x;
    const int lane = t & 31, w = t >> 5;
    const int gid = lane >> 2, tig = lane & 3;
    const int nqc = S_LEN / AQT;               // 32
    const int qc = blockIdx.x % nqc;
    const int hh = (blockIdx.x / nqc) % NH;
    const int b  = blockIdx.x / (nqc * NH);
    const int qi0 = qc * AQT;

    {
        int r = t >> 1, c0 = (t & 1) * 32;
        const float* qp = g_qkv + ((size_t)(b * S_LEN + qi0 + r) * NH + hh) * 192 + c0;
        uint32_t* qs = sw + QS_OFF + r * QSTR + c0;
#pragma unroll
        for (int i = 0; i < 8; i++) {
            float4 v = *(const float4*)(qp + 4 * i);
            *(uint4*)(qs + 4 * i) =
                make_uint4(cvt_tf32(v.x), cvt_tf32(v.y), cvt_tf32(v.z), cvt_tf32(v.w));
        }
    }

    const int kt_lo = (qi0 < WRAD) ? (WRAD - qi0) / AKT : 0;
    const int kt_hi = min(ATILES - 1, (S_LEN + WRAD - AKT - qi0) / AKT);

    float oacc[8][4];
#pragma unroll
    for (int nj = 0; nj < 8; nj++)
#pragma unroll
        for (int e = 0; e < 4; e++) oacc[nj][e] = 0.f;
    float m[2] = {-1e30f, -1e30f};
    float lp[2] = {0.f, 0.f};

    const int row0 = qi0 + w * 16 + gid;
    const uint32_t* qbase = sw + QS_OFF + (w * 16 + gid) * QSTR;

    swa_load_kv(b, hh, qi0 - WRAD + kt_lo * AKT, sw, 0, t);
    int pb = 0;

    for (int kt = kt_lo; kt <= kt_hi; kt++) {
        const int ks = qi0 - WRAD + kt * AKT;
        const bool pf = (kt < kt_hi);
        __syncthreads();

        const uint32_t* Kb = sw + KB_OFF + pb * (64 * KSTR);
        const uint32_t* Vb = sw + VB_OFF + pb * (64 * VSTR);

        float sacc[8][4];
#pragma unroll
        for (int nj = 0; nj < 8; nj++)
#pragma unroll
            for (int e = 0; e < 4; e++) sacc[nj][e] = 0.f;

#pragma unroll
        for (int kk = 0; kk < 8; kk++) {
            uint32_t a[4];
            const uint32_t* qrow = qbase + kk * 8;
            a[0] = qrow[tig];
            a[1] = qrow[8 * QSTR + tig];
            a[2] = qrow[tig + 4];
            a[3] = qrow[8 * QSTR + tig + 4];
#pragma unroll
            for (int nj = 0; nj < 8; nj++) {
                const uint32_t* krow = Kb + (nj * 8 + gid) * KSTR + kk * 8;
                uint32_t bfr[2] = {krow[tig], krow[tig + 4]};
                mma_tf32(sacc[nj], a, bfr);
            }
        }

        if (pf) {
            const int kr = t >> 2, kc = (t & 3) * 16;
            const float* np = g_qkv +
                ((size_t)(b * S_LEN + ks + AKT + kr) * NH + hh) * 192 + 64 + kc;
            prefetch_l2(np);
            prefetch_l2(np + 64);
        }

        float mt[2] = {-1e30f, -1e30f};
#pragma unroll
        for (int nj = 0; nj < 8; nj++)
#pragma unroll
            for (int e = 0; e < 4; e++) {
                int col = ks + nj * 8 + 2 * tig + (e & 1);
                int d = col - (row0 + (e >> 1) * 8);
                bool val = (d >= -WRAD) && (d <= WRAD);
                float sv = val ? sacc[nj][e] * 0.125f : -1e30f;
                sacc[nj][e] = sv;
                mt[e >> 1] = fmaxf(mt[e >> 1], sv);
            }
#pragma unroll
        for (int hE = 0; hE < 2; hE++) {
            mt[hE] = fmaxf(mt[hE], __shfl_xor_sync(0xffffffffu, mt[hE], 1));
            mt[hE] = fmaxf(mt[hE], __shfl_xor_sync(0xffffffffu, mt[hE], 2));
            float mn = fmaxf(m[hE], mt[hE]);
            float corr = __expf(m[hE] - mn);
            m[hE] = mn;
            lp[hE] *= corr;
#pragma unroll
            for (int nj = 0; nj < 8; nj++) {
                oacc[nj][2 * hE]     *= corr;
                oacc[nj][2 * hE + 1] *= corr;
            }
        }

        uint32_t pu[8][4];
#pragma unroll
        for (int nj = 0; nj < 8; nj++)
#pragma unroll
            for (int e = 0; e < 4; e++) {
                float p = (sacc[nj][e] > -1e29f)
                        ? __expf(sacc[nj][e] - m[e >> 1]) : 0.f;
                lp[e >> 1] += p;
                pu[nj][e] = cvt_tf32(p);
            }

#pragma unroll
        for (int kk = 0; kk < 8; kk++) {
            uint32_t a[4];
            int src0 = (lane & ~3) | (tig >> 1);
            int src1 = src0 | 2;
            uint32_t x00 = __shfl_sync(0xffffffffu, pu[kk][0], src0);
            uint32_t x01 = __shfl_sync(0xffffffffu, pu[kk][1], src0);
            uint32_t x02 = __shfl_sync(0xffffffffu, pu[kk][2], src0);
            uint32_t x03 = __shfl_sync(0xffffffffu, pu[kk][3], src0);
            uint32_t x10 = __shfl_sync(0xffffffffu, pu[kk][0], src1);
            uint32_t x11 = __shfl_sync(0xffffffffu, pu[kk][1], src1);
            uint32_t x12 = __shfl_sync(0xffffffffu, pu[kk][2], src1);
            uint32_t x13 = __shfl_sync(0xffffffffu, pu[kk][3], src1);
            a[0] = (tig & 1) ? x01 : x00;
            a[1] = (tig & 1) ? x03 : x02;
            a[2] = (tig & 1) ? x11 : x10;
            a[3] = (tig & 1) ? x13 : x12;
#pragma unroll
            for (int nj = 0; nj < 8; nj++) {
                const uint32_t* vrow = Vb + (kk * 8 + tig) * VSTR + nj * 8 + gid;
                uint32_t bfr[2] = {vrow[0], vrow[4 * VSTR]};
                mma_tf32(oacc[nj], a, bfr);
            }
        }

        if (pf) {
            swa_load_kv(b, hh, ks + AKT, sw, pb ^ 1, t);
            pb ^= 1;
        }
    }

    float linv[2];
#pragma unroll
    for (int hE = 0; hE < 2; hE++) {
        float l = lp[hE];
        l += __shfl_xor_sync(0xffffffffu, l, 1);
        l += __shfl_xor_sync(0xffffffffu, l, 2);
        linv[hE] = 1.0f / l;
    }
#pragma unroll
    for (int nj = 0; nj < 8; nj++) {
        int col = nj * 8 + 2 * tig;
        float* op = g_ctx + (size_t)(b * S_LEN + row0) * EMB + hh * HD + col;
        *(float2*)op = make_float2(
            __uint_as_float(cvt_tf32(oacc[nj][0] * linv[0])),
            __uint_as_float(cvt_tf32(oacc[nj][1] * linv[0])));
        *(float2*)(op + (size_t)8 * EMB) = make_float2(
            __uint_as_float(cvt_tf32(oacc[nj][2] * linv[1])),
            __uint_as_float(cvt_tf32(oacc[nj][3] * linv[1])));
    }
}

// ---------------- launch ----------------------------------------------------
extern "C" void kernel_launch(void* const* d_in, const int* in_sizes, int n_in,
                              void* d_out, int out_size) {
    const float* x    = (const float*)d_in[0];
    const float* Wqkv = (const float*)d_in[1];
    const float* bqkv = (const float*)d_in[2];
    const float* Wo   = (const float*)d_in[3];
    const float* bo   = (const float*)d_in[4];
    float* out = (float*)d_out;

    float *qkv, *ctx, *xr, *wq, *wo;
    cudaGetSymbolAddress((void**)&qkv, g_qkv);
    cudaGetSymbolAddress((void**)&ctx, g_ctx);
    cudaGetSymbolAddress((void**)&xr,  g_x);
    cudaGetSymbolAddress((void**)&wq,  g_wq);
    cudaGetSymbolAddress((void**)&wo,  g_wo);

    const int M = BATCH * S_LEN;   // 8192

    cudaFuncSetAttribute(gemm_tf32, cudaFuncAttributeMaxDynamicSharedMemorySize, GEMM_SMEM);
    cudaFuncSetAttribute(swa_mma, cudaFuncAttributeMaxDynamicSharedMemorySize, ASMEM);

    round_tf32_k<<<(M * EMB) / 1024, 256>>>(x, xr);
    round_tf32_k<<<(EMB * QKV_N) / 1024, 256>>>(Wqkv, wq);
    round_tf32_k<<<(EMB * EMB) / 1024, 256>>>(Wo, wo);

    gemm_tf32<<<dim3(QKV_N / BN, M / BM), 256, GEMM_SMEM>>>(xr, wq, bqkv, qkv, M, QKV_N, EMB);

    swa_mma<<<BATCH * NH * (S_LEN / AQT), 256, ASMEM>>>();

    gemm_tf32<<<dim3(EMB / BN, M / BM), 256, GEMM_SMEM>>>(ctx, wo, bo, out, M, EMB, EMB);
}